// round 1
// baseline (speedup 1.0000x reference)
#include <cuda_runtime.h>
#include <cstdint>

#define BB   16
#define CC   128
#define HH   28
#define WW   28
#define FF   128
#define KK   1152      // CC*9
#define LL   784       // 28*28
#define LPAD 832       // 13*64
#define FT   64
#define LT   64
#define KC   32
#define NKC  (KK/KC)   // 36

// Scratch (allocation-free rule: __device__ globals)
__device__ __align__(16) float g_Pneg[(size_t)BB * KK * LPAD];  // -patches, zero padded
__device__ __align__(16) float g_Wt[KK * FF];                   // W transposed [K][F]

// ---------------- im2col (negated) ----------------
__global__ void im2col_kernel(const float* __restrict__ x) {
    int idx = blockIdx.x * blockDim.x + threadIdx.x;       // one thread per 4 lp
    int total = BB * KK * (LPAD / 4);
    if (idx >= total) return;
    int lp4 = idx % (LPAD / 4);
    int bk  = idx / (LPAD / 4);
    int k = bk % KK;
    int b = bk / KK;
    int c  = k / 9;
    int r  = k % 9;
    int kh = r / 3, kw = r % 3;
    const float* xp = x + ((size_t)(b * CC + c)) * HH * WW;
    int lp0 = lp4 * 4;
    float4 v;
    float* vv = reinterpret_cast<float*>(&v);
#pragma unroll
    for (int j = 0; j < 4; j++) {
        int l = lp0 + j;
        float val = 0.0f;
        if (l < LL) {
            int oh = l / WW, ow = l % WW;
            int ih = oh + kh - 1, iw = ow + kw - 1;
            if (ih >= 0 && ih < HH && iw >= 0 && iw < WW) val = xp[ih * WW + iw];
        }
        vv[j] = -val;
    }
    *reinterpret_cast<float4*>(&g_Pneg[((size_t)(b * KK + k)) * LPAD + lp0]) = v;
}

// ---------------- W transpose ----------------
__global__ void wtrans_kernel(const float* __restrict__ Wg) {
    int idx = blockIdx.x * blockDim.x + threadIdx.x;
    if (idx >= FF * KK) return;
    int k = idx % KK, f = idx / KK;
    g_Wt[k * FF + f] = Wg[f * KK + k];
}

// ---------------- packed f32x2 helpers ----------------
__device__ __forceinline__ unsigned long long add2(unsigned long long a, unsigned long long b) {
    unsigned long long r;
    asm("add.rn.f32x2 %0, %1, %2;" : "=l"(r) : "l"(a), "l"(b));
    return r;
}
__device__ __forceinline__ unsigned long long pack2(float lo, float hi) {
    unsigned long long r;
    asm("mov.b64 %0, {%1, %2};" : "=l"(r) : "r"(__float_as_uint(lo)), "r"(__float_as_uint(hi)));
    return r;
}
__device__ __forceinline__ void unpack2(unsigned long long v, float& lo, float& hi) {
    unsigned int a, b;
    asm("mov.b64 {%0, %1}, %2;" : "=r"(a), "=r"(b) : "l"(v));
    lo = __uint_as_float(a);
    hi = __uint_as_float(b);
}

#define CPA16(s, g) asm volatile("cp.async.ca.shared.global [%0], [%1], 16;\n" :: "r"(s), "l"(g))

// ---------------- main L1-distance kernel ----------------
__global__ void __launch_bounds__(256) adder_kernel(float* __restrict__ out) {
    __shared__ __align__(16) float sW[2][KC][FT];
    __shared__ __align__(16) float sP[2][KC][LT];

    const int tid = threadIdx.x;
    const int b  = blockIdx.z;
    const int f0 = blockIdx.y * FT;
    const int l0 = blockIdx.x * LT;

    const float* gW = g_Wt;                                 // [K][F]
    const float* gP = g_Pneg + (size_t)b * KK * LPAD;       // [K][LPAD]

    // fill mapping: per stage, W tile = 32x64 floats = 512 float4, P tile same.
    // each thread copies 2 float4 of W and 2 float4 of P.
    const int wr0 = tid >> 4;            // 0..15
    const int wr1 = wr0 + 16;            // 16..31
    const int wc  = (tid & 15) * 4;      // 0..60

    const uint32_t sW_base = (uint32_t)__cvta_generic_to_shared(&sW[0][0][0]);
    const uint32_t sP_base = (uint32_t)__cvta_generic_to_shared(&sP[0][0][0]);

    auto fill = [&](int s) {
        int buf = s & 1;
        int k0 = s * KC;
        uint32_t dW0 = sW_base + (uint32_t)(((buf * KC + wr0) * FT + wc) * 4);
        uint32_t dW1 = sW_base + (uint32_t)(((buf * KC + wr1) * FT + wc) * 4);
        CPA16(dW0, gW + (size_t)(k0 + wr0) * FF + f0 + wc);
        CPA16(dW1, gW + (size_t)(k0 + wr1) * FF + f0 + wc);
        uint32_t dP0 = sP_base + (uint32_t)(((buf * KC + wr0) * LT + wc) * 4);
        uint32_t dP1 = sP_base + (uint32_t)(((buf * KC + wr1) * LT + wc) * 4);
        CPA16(dP0, gP + (size_t)(k0 + wr0) * LPAD + l0 + wc);
        CPA16(dP1, gP + (size_t)(k0 + wr1) * LPAD + l0 + wc);
        asm volatile("cp.async.commit_group;\n" ::: "memory");
    };

    const int tf = (tid & 15) * 4;   // this thread's 4 consecutive f within tile
    const int tl = (tid >> 4) * 4;   // this thread's 4 consecutive l within tile

    unsigned long long acc[4][2];
#pragma unroll
    for (int i = 0; i < 4; i++) { acc[i][0] = 0ULL; acc[i][1] = 0ULL; }

    const unsigned long long ABSM = 0x7FFFFFFF7FFFFFFFULL;

    fill(0);
    for (int s = 0; s < NKC; s++) {
        asm volatile("cp.async.wait_group 0;\n" ::: "memory");
        __syncthreads();
        if (s + 1 < NKC) fill(s + 1);
        const int buf = s & 1;
#pragma unroll
        for (int kc = 0; kc < KC; kc++) {
            float4 wv = *reinterpret_cast<const float4*>(&sW[buf][kc][tf]);
            float4 pv = *reinterpret_cast<const float4*>(&sP[buf][kc][tl]);
            unsigned long long p0 = pack2(pv.x, pv.y);   // negated patches
            unsigned long long p1 = pack2(pv.z, pv.w);
            float wvv[4] = {wv.x, wv.y, wv.z, wv.w};
#pragma unroll
            for (int i = 0; i < 4; i++) {
                unsigned long long w2 = pack2(wvv[i], wvv[i]);
                unsigned long long d0 = add2(w2, p0) & ABSM;   // |w - p| packed
                unsigned long long d1 = add2(w2, p1) & ABSM;
                acc[i][0] = add2(acc[i][0], d0);
                acc[i][1] = add2(acc[i][1], d1);
            }
        }
    }

    // epilogue: out = -sum
    const int lbase = l0 + tl;
    if (lbase < LL) {   // LL % 4 == 0 → whole float4 valid or invalid
#pragma unroll
        for (int i = 0; i < 4; i++) {
            float a0, a1, a2, a3;
            unpack2(acc[i][0], a0, a1);
            unpack2(acc[i][1], a2, a3);
            float4 v = make_float4(-a0, -a1, -a2, -a3);
            int f = f0 + tf + i;
            *reinterpret_cast<float4*>(&out[((size_t)(b * FF + f)) * LL + lbase]) = v;
        }
    }
}

extern "C" void kernel_launch(void* const* d_in, const int* in_sizes, int n_in,
                              void* d_out, int out_size) {
    const float* x  = (const float*)d_in[0];   // [16,128,28,28]
    const float* Wg = (const float*)d_in[1];   // [128,128,3,3]
    float* out = (float*)d_out;                // [16,128,28,28]

    int n1 = BB * KK * (LPAD / 4);
    im2col_kernel<<<(n1 + 255) / 256, 256>>>(x);
    wtrans_kernel<<<(FF * KK + 255) / 256, 256>>>(Wg);

    dim3 grid(LPAD / LT /*13*/, FF / FT /*2*/, BB /*16*/);
    adder_kernel<<<grid, 256>>>(out);
}